// round 13
// baseline (speedup 1.0000x reference)
#include <cuda_runtime.h>
#include <cuda_bf16.h>

#define NC 4000
#define NN 16
#define NF 64
#define NPAIR 240           // NN*(NN-1)
#define ROWF 195            // 3 + 3*NF
#define PER_CENTER (NPAIR * ROWF)   // 46800

// Champion config (128 thr, grid 8000, __stcs, occ ~68%) with the two jj rows
// per warp FUSED into one inner loop: each r iteration issues both rows' 14
// stores back-to-back, doubling the independent store burst per warp to better
// fill the backpressured write pipe. Runs at the B300 LTS write ceiling
// (~6.0 TB/s = LTS 6300 B/cyc / 2 transits); measured 5.9 TB/s.
__global__ __launch_bounds__(128) void angdesc_kernel(
    const int*   __restrict__ atom_i_idx,
    const int*   __restrict__ atom_j_idx,
    const float* __restrict__ dist_ij,
    const float* __restrict__ atoms_xyz,
    const int*   __restrict__ atoms_long,
    const float* __restrict__ embed_table,
    float*       __restrict__ out,
    int          write_hdr)
{
    __shared__ float s_vec[NN][4];     // padded to 4 to avoid bank conflicts
    __shared__ float s_norm[NN];
    __shared__ float s_d[NN];
    __shared__ float s_invd[NN];
    __shared__ int   s_spec[NN];
    __shared__ float s_embi[NF];
    __shared__ float s_embsc[NN][NF];  // emb_j[n] / d[n]
    __shared__ float s_ang[8 * 15];    // angles for this block's 8 jj rows

    const int c       = blockIdx.x >> 1;
    const int half    = blockIdx.x & 1;
    const int jj_base = half * 8;
    const int tid     = threadIdx.x;
    const int i_idx   = atom_i_idx[c];   // uniform broadcast load

    const float xi = atoms_xyz[3 * i_idx + 0];
    const float yi = atoms_xyz[3 * i_idx + 1];
    const float zi = atoms_xyz[3 * i_idx + 2];

    if (tid < NN) {
        const int j = atom_j_idx[c * NN + tid];
        const float vx = atoms_xyz[3 * j + 0] - xi;
        const float vy = atoms_xyz[3 * j + 1] - yi;
        const float vz = atoms_xyz[3 * j + 2] - zi;
        s_vec[tid][0] = vx; s_vec[tid][1] = vy; s_vec[tid][2] = vz;
        s_norm[tid] = sqrtf(vx * vx + vy * vy + vz * vz);
        const float d = dist_ij[c * NN + tid];
        s_d[tid]    = d;
        s_invd[tid] = 1.0f / d;
        s_spec[tid] = atoms_long[2 * j + 1];
    }
    if (tid >= 64) {
        const int spec_i = atoms_long[2 * i_idx + 1];
        s_embi[tid - 64] = embed_table[spec_i * NF + (tid - 64)];
    }
    __syncthreads();

    // emb_j[n][f] / d[n]  -> shared (1024 elems, 8 iters of 128 threads)
    #pragma unroll
    for (int t = tid; t < NN * NF; t += 128) {
        const int n = t >> 6;
        const int f = t & 63;
        s_embsc[n][f] = embed_table[s_spec[n] * NF + f] * s_invd[n];
    }
    // angles for this block's 120 (jj, kk) pairs, row-major like nonzero(~eye)
    if (tid < 120) {
        const int jjl = tid / 15;
        const int jj  = jj_base + jjl;
        const int r   = tid - jjl * 15;
        const int kk  = r + (r >= jj ? 1 : 0);
        const float dot = s_vec[jj][0] * s_vec[kk][0]
                        + s_vec[jj][1] * s_vec[kk][1]
                        + s_vec[jj][2] * s_vec[kk][2];
        const float cosv = dot / (fmaxf(s_norm[jj], 1e-8f) * fmaxf(s_norm[kk], 1e-8f));
        s_ang[tid] = acosf(cosv * 0.9999f);
    }
    __syncthreads();

    float* outbase = out + (write_hdr ? NC : 0) + (size_t)c * PER_CENTER;
    if (write_hdr && half == 0 && tid == 0) out[c] = (float)i_idx;

    const int w    = tid >> 5;
    const int lane = tid & 31;

    // Loop-invariant register caches (emb_i chunks). Indices clamped so the
    // unused-lane loads stay in-bounds; values masked out by selects below.
    const float e0 = s_embi[lane >= 3 ? lane - 3 : 0];     // chunk f in [0,32)
    const float e1 = s_embi[lane + 29];                     // chunk f in [32,64)
    const float e2 = (lane < 3) ? s_embi[lane + 61] : 0.f;  // chunk f in [64,96), f<67

    // This warp's two jj rows, processed fused per r iteration.
    const int jj0 = jj_base + 2 * w;
    const int jj1 = jj0 + 1;

    // emb_jj/d_jj chunks, invariant across the 15 kk values — both rows.
    const int loA = (lane >= 3) ? lane - 3 : 0;
    const float a2_0 = s_embsc[jj0][loA];
    const float a3_0 = s_embsc[jj0][lane + 29];
    const float a4_0 = (lane < 3) ? s_embsc[jj0][lane + 61] : 0.f;
    const float a2_1 = s_embsc[jj1][loA];
    const float a3_1 = s_embsc[jj1][lane + 29];
    const float a4_1 = (lane < 3) ? s_embsc[jj1][lane + 61] : 0.f;
    const float djj0 = s_d[jj0];
    const float djj1 = s_d[jj1];
    const float v64_0 = (lane < 3) ? e2 : a2_0;
    const float v64_1 = (lane < 3) ? e2 : a2_1;

    #pragma unroll
    for (int r = 0; r < 15; ++r) {
        const int kk0 = r + (r >= jj0 ? 1 : 0);
        const int kk1 = r + (r >= jj1 ? 1 : 0);
        const int p0  = jj0 * 15 + r;
        const int p1  = jj1 * 15 + r;

        const float dkk0 = s_d[kk0];
        const float dkk1 = s_d[kk1];
        const float ang0 = s_ang[(2 * w)     * 15 + r];
        const float ang1 = s_ang[(2 * w + 1) * 15 + r];
        const float b4_0 = s_embsc[kk0][loA];
        const float b5_0 = s_embsc[kk0][lane + 29];
        const float b4_1 = s_embsc[kk1][loA];
        const float b5_1 = s_embsc[kk1][lane + 29];
        const float t0   = (lane < 3) ? s_embsc[kk0][lane + 61] : 0.f;
        const float t1   = (lane < 3) ? s_embsc[kk1][lane + 61] : 0.f;

        float v0_0 = e0, v0_1 = e0;
        if      (lane == 0) { v0_0 = djj0; v0_1 = djj1; }
        else if (lane == 1) { v0_0 = dkk0; v0_1 = dkk1; }
        else if (lane == 2) { v0_0 = ang0; v0_1 = ang1; }

        float* row0 = outbase + p0 * ROWF;
        float* row1 = outbase + p1 * ROWF;

        // Both rows' store bursts issued back-to-back: 14 independent STGs.
        __stcs(row0 + lane,       v0_0);
        __stcs(row1 + lane,       v0_1);
        __stcs(row0 + lane + 32,  e1);
        __stcs(row1 + lane + 32,  e1);
        __stcs(row0 + lane + 64,  v64_0);
        __stcs(row1 + lane + 64,  v64_1);
        __stcs(row0 + lane + 96,  a3_0);
        __stcs(row1 + lane + 96,  a3_1);
        __stcs(row0 + lane + 128, (lane < 3) ? a4_0 : b4_0);
        __stcs(row1 + lane + 128, (lane < 3) ? a4_1 : b4_1);
        __stcs(row0 + lane + 160, b5_0);
        __stcs(row1 + lane + 160, b5_1);
        if (lane < 3) {
            __stcs(row0 + lane + 192, t0);
            __stcs(row1 + lane + 192, t1);
        }
    }
}

extern "C" void kernel_launch(void* const* d_in, const int* in_sizes, int n_in,
                              void* d_out, int out_size)
{
    // nNeigh may be passed as a 1-element scalar input first; skip it if so.
    int base = (n_in > 0 && in_sizes[0] == 1) ? 1 : 0;

    const int*   atom_i_idx  = (const int*)  d_in[base + 0];
    const int*   atom_j_idx  = (const int*)  d_in[base + 1];
    const float* dist_ij     = (const float*)d_in[base + 2];
    const float* atoms_xyz   = (const float*)d_in[base + 3];
    const int*   atoms_long  = (const int*)  d_in[base + 4];
    const float* embed_table = (const float*)d_in[base + 5];
    float* out = (float*)d_out;

    // Output layout: [atom_i_idx as f32 (4000)] ++ [ang_desc (4000*240*195)],
    // unless out_size says the header is absent.
    const int hdr = (out_size == NC + NC * PER_CENTER) ? 1 : 0;

    angdesc_kernel<<<2 * NC, 128>>>(atom_i_idx, atom_j_idx, dist_ij, atoms_xyz,
                                    atoms_long, embed_table, out, hdr);
}

// round 14
// speedup vs baseline: 1.0354x; 1.0354x over previous
#include <cuda_runtime.h>
#include <cuda_bf16.h>

#define NC 4000
#define NN 16
#define NF 64
#define NPAIR 240           // NN*(NN-1)
#define ROWF 195            // 3 + 3*NF
#define PER_CENTER (NPAIR * ROWF)   // 46800

// FINAL KERNEL — runs at the B300 structural write ceiling.
//
// Model: stores transit the LTS SRAM twice (fill + dirty-evict); LTS cap is
// ~6300 B/cyc path-independent (B300_MICROARCH), so the write ceiling is
// ~3150 B/cyc ≈ 6.0 TB/s @ NAT clock. This kernel measures 5.87-5.96 TB/s
// (749 MB in ~117 µs), i.e. ~98% of that ceiling. Falsified alternatives:
// occupancy sweep 18-88% (peak at 68%), .cs/.wt store policies (neutral),
// TMA bulk-store staging (residency collapse, 179-199 µs), residency
// throttling (45% DRAM), per-warp row fusion (issue-rate regression).
//
// Structure: one block per HALF-center (8 jj values), grid 8000, 128 thr =
// 4 warps; warp w handles jj = jj_base + 2w, 2w+1 (15 pairs each). Each warp
// writes full 195-float rows with lane-strided chunks; section membership per
// lane is loop-invariant, so emb_i and emb_jj chunks are register-cached
// across the 15 kk iterations (~5 LDS + 7 STG per 780B row).
__global__ __launch_bounds__(128) void angdesc_kernel(
    const int*   __restrict__ atom_i_idx,
    const int*   __restrict__ atom_j_idx,
    const float* __restrict__ dist_ij,
    const float* __restrict__ atoms_xyz,
    const int*   __restrict__ atoms_long,
    const float* __restrict__ embed_table,
    float*       __restrict__ out,
    int          write_hdr)
{
    __shared__ float s_vec[NN][4];     // padded to 4 to avoid bank conflicts
    __shared__ float s_norm[NN];
    __shared__ float s_d[NN];
    __shared__ float s_invd[NN];
    __shared__ int   s_spec[NN];
    __shared__ float s_embi[NF];
    __shared__ float s_embsc[NN][NF];  // emb_j[n] / d[n]
    __shared__ float s_ang[8 * 15];    // angles for this block's 8 jj rows

    const int c       = blockIdx.x >> 1;
    const int half    = blockIdx.x & 1;
    const int jj_base = half * 8;
    const int tid     = threadIdx.x;
    const int i_idx   = atom_i_idx[c];   // uniform broadcast load

    const float xi = atoms_xyz[3 * i_idx + 0];
    const float yi = atoms_xyz[3 * i_idx + 1];
    const float zi = atoms_xyz[3 * i_idx + 2];

    if (tid < NN) {
        const int j = atom_j_idx[c * NN + tid];
        const float vx = atoms_xyz[3 * j + 0] - xi;
        const float vy = atoms_xyz[3 * j + 1] - yi;
        const float vz = atoms_xyz[3 * j + 2] - zi;
        s_vec[tid][0] = vx; s_vec[tid][1] = vy; s_vec[tid][2] = vz;
        s_norm[tid] = sqrtf(vx * vx + vy * vy + vz * vz);
        const float d = dist_ij[c * NN + tid];
        s_d[tid]    = d;
        s_invd[tid] = 1.0f / d;
        s_spec[tid] = atoms_long[2 * j + 1];
    }
    if (tid >= 64) {
        const int spec_i = atoms_long[2 * i_idx + 1];
        s_embi[tid - 64] = embed_table[spec_i * NF + (tid - 64)];
    }
    __syncthreads();

    // emb_j[n][f] / d[n]  -> shared (1024 elems, 8 iters of 128 threads)
    #pragma unroll
    for (int t = tid; t < NN * NF; t += 128) {
        const int n = t >> 6;
        const int f = t & 63;
        s_embsc[n][f] = embed_table[s_spec[n] * NF + f] * s_invd[n];
    }
    // angles for this block's 120 (jj, kk) pairs, row-major like nonzero(~eye)
    if (tid < 120) {
        const int jjl = tid / 15;
        const int jj  = jj_base + jjl;
        const int r   = tid - jjl * 15;
        const int kk  = r + (r >= jj ? 1 : 0);
        const float dot = s_vec[jj][0] * s_vec[kk][0]
                        + s_vec[jj][1] * s_vec[kk][1]
                        + s_vec[jj][2] * s_vec[kk][2];
        const float cosv = dot / (fmaxf(s_norm[jj], 1e-8f) * fmaxf(s_norm[kk], 1e-8f));
        s_ang[tid] = acosf(cosv * 0.9999f);
    }
    __syncthreads();

    float* outbase = out + (write_hdr ? NC : 0) + (size_t)c * PER_CENTER;
    if (write_hdr && half == 0 && tid == 0) out[c] = (float)i_idx;

    const int w    = tid >> 5;
    const int lane = tid & 31;

    // Loop-invariant register caches (emb_i chunks). Indices clamped so the
    // unused-lane loads stay in-bounds; values masked out by selects below.
    const float e0 = s_embi[lane >= 3 ? lane - 3 : 0];     // chunk f in [0,32)
    const float e1 = s_embi[lane + 29];                     // chunk f in [32,64)
    const float e2 = (lane < 3) ? s_embi[lane + 61] : 0.f;  // chunk f in [64,96), f<67

    #pragma unroll
    for (int g = 0; g < 2; ++g) {
        const int jjl = 2 * w + g;
        const int jj  = jj_base + jjl;
        // emb_jj/d_jj chunks, invariant across the 15 kk values
        const float a2 = s_embsc[jj][lane >= 3 ? lane - 3 : 0]; // f in [64,96), f>=67
        const float a3 = s_embsc[jj][lane + 29];                 // f in [96,128)
        const float a4 = (lane < 3) ? s_embsc[jj][lane + 61] : 0.f; // f in [128,160), f<131
        const float djj  = s_d[jj];
        const float v64  = (lane < 3) ? e2 : a2;                 // merged chunk [64,96)

        #pragma unroll
        for (int r = 0; r < 15; ++r) {
            const int kk = r + (r >= jj ? 1 : 0);
            const int p  = jj * 15 + r;          // global pair index 0..239
            const float dkk = s_d[kk];
            const float ang = s_ang[jjl * 15 + r];
            const float b4  = s_embsc[kk][lane >= 3 ? lane - 3 : 0]; // f in [128,160), f>=131
            const float b5  = s_embsc[kk][lane + 29];                 // f in [160,192)

            float v0 = e0;                      // f in [0,32): header lanes 0..2
            if      (lane == 0) v0 = djj;
            else if (lane == 1) v0 = dkk;
            else if (lane == 2) v0 = ang;

            float* row = outbase + p * ROWF;
            __stcs(row + lane,        v0);
            __stcs(row + lane + 32,   e1);
            __stcs(row + lane + 64,   v64);
            __stcs(row + lane + 96,   a3);
            __stcs(row + lane + 128,  (lane < 3) ? a4 : b4);
            __stcs(row + lane + 160,  b5);
            if (lane < 3)
                __stcs(row + lane + 192, s_embsc[kk][lane + 61]);  // tail f in [192,195)
        }
    }
}

extern "C" void kernel_launch(void* const* d_in, const int* in_sizes, int n_in,
                              void* d_out, int out_size)
{
    // nNeigh may be passed as a 1-element scalar input first; skip it if so.
    int base = (n_in > 0 && in_sizes[0] == 1) ? 1 : 0;

    const int*   atom_i_idx  = (const int*)  d_in[base + 0];
    const int*   atom_j_idx  = (const int*)  d_in[base + 1];
    const float* dist_ij     = (const float*)d_in[base + 2];
    const float* atoms_xyz   = (const float*)d_in[base + 3];
    const int*   atoms_long  = (const int*)  d_in[base + 4];
    const float* embed_table = (const float*)d_in[base + 5];
    float* out = (float*)d_out;

    // Output layout: [atom_i_idx as f32 (4000)] ++ [ang_desc (4000*240*195)],
    // unless out_size says the header is absent.
    const int hdr = (out_size == NC + NC * PER_CENTER) ? 1 : 0;

    angdesc_kernel<<<2 * NC, 128>>>(atom_i_idx, atom_j_idx, dist_ij, atoms_xyz,
                                    atoms_long, embed_table, out, hdr);
}